// round 1
// baseline (speedup 1.0000x reference)
#include <cuda_runtime.h>

#define D 128
#define NTOT ((1 << 18) - 1)      // 262143
#define LEAF0 ((1 << 17) - 1)     // first leaf index 131071

// Scratch: raw (embed output, = emb/ret for leaves) and emb (h for internal nodes).
__device__ float g_raw[NTOT * D];   // 134 MB
__device__ float g_emb[NTOT * D];   // 134 MB (only internal nodes written)

// ---------------------------------------------------------------------------
// Embed: raw[i] = data_vecs[data[i]] @ data_W + data_b
// data_W cached in SMEM; each warp processes 4 nodes per W read (FFMA-bound).
// ---------------------------------------------------------------------------
__global__ void embed_kernel(const int* __restrict__ data,
                             const float* __restrict__ data_vecs,
                             const float* __restrict__ data_W,
                             const float* __restrict__ data_b)
{
    extern __shared__ float sm[];
    float* Wsh = sm;                       // 16384 floats (64 KB)
    float* vsh = sm + 16384;               // 8 warps * 4 rows * 128 = 4096
    float* bsh = vsh + 4096;               // 128
    const int tid  = threadIdx.x;
    const int w    = tid >> 5;
    const int lane = tid & 31;

    {
        const float4* W4 = (const float4*)data_W;
        float4* Wsh4w = (float4*)Wsh;
        for (int i = tid; i < 4096; i += 256) Wsh4w[i] = W4[i];
        if (tid < D) bsh[tid] = data_b[tid];
    }
    __syncthreads();

    const float4* Wsh4 = (const float4*)Wsh;
    float* vrow = vsh + w * 512;
    const float4 b4 = ((const float4*)bsh)[lane];

    const int gw = blockIdx.x * 8 + w;
    const int nw = gridDim.x * 8;
    for (int base = gw * 4; base < NTOT; base += nw * 4) {
        const int nvalid = min(4, NTOT - base);
        #pragma unroll
        for (int t = 0; t < 4; ++t) {
            int node = base + min(t, nvalid - 1);   // clamp (dup load ok)
            int v = data[node];
            ((float4*)(vrow + t * 128))[lane] =
                ((const float4*)(data_vecs + (size_t)v * D))[lane];
        }
        __syncwarp();
        float a[4][4];
        #pragma unroll
        for (int t = 0; t < 4; ++t) { a[t][0]=0.f; a[t][1]=0.f; a[t][2]=0.f; a[t][3]=0.f; }
        #pragma unroll 4
        for (int k = 0; k < D; ++k) {
            float4 wv = Wsh4[k * 32 + lane];
            #pragma unroll
            for (int t = 0; t < 4; ++t) {
                float vk = vrow[t * 128 + k];
                a[t][0] += vk * wv.x; a[t][1] += vk * wv.y;
                a[t][2] += vk * wv.z; a[t][3] += vk * wv.w;
            }
        }
        #pragma unroll
        for (int t = 0; t < 4; ++t) {
            if (t < nvalid) {
                float4 o = make_float4(a[t][0] + b4.x, a[t][1] + b4.y,
                                       a[t][2] + b4.z, a[t][3] + b4.w);
                ((float4*)(g_raw + (size_t)(base + t) * D))[lane] = o;
            }
        }
        __syncwarp();
    }
}

// ---------------------------------------------------------------------------
// One tree level. Block = 64 parents (128 children), 256 threads.
// Loop e = 0..7: edge_W[e] in SMEM; each warp owns 8 parents (16 children),
// processes its matching children in groups of up to 4 per W read.
// h[parent] = (raw[parent] + sum_children(edge_b[e] + ret_child @ edge_W[e])) / 3
// ret_child = raw (leaf children) or max(emb, 0) (internal children).
// ---------------------------------------------------------------------------
__global__ void level_kernel(const int* __restrict__ edges,
                             const float* __restrict__ edge_W,
                             const float* __restrict__ edge_b,
                             int p0, int npar, int child_is_leaf)
{
    extern __shared__ float sm[];
    float* Wsh = sm;                 // 16384 floats
    float* csh = sm + 16384;         // 64 * 128 = 8192 (parent contribs)
    float* vsh = csh + 8192;         // 8 warps * 4 rows * 128 = 4096
    __shared__ unsigned s_pres;

    const int tid  = threadIdx.x;
    const int w    = tid >> 5;
    const int lane = tid & 31;
    const int pbase = blockIdx.x * 64;

    if (tid == 0) s_pres = 0u;
    for (int i = tid; i < 8192; i += 256) csh[i] = 0.f;

    // Per-warp child edge ids (uniform across lanes — same addresses).
    int eArr[16];
    unsigned warpPres = 0u;
    #pragma unroll
    for (int idx = 0; idx < 16; ++idx) {
        int i = w + (idx >> 1) * 8;
        if (pbase + i < npar) {
            int c = 2 * (p0 + pbase + i) + 1 + (idx & 1);
            eArr[idx] = edges[c];
            warpPres |= (1u << eArr[idx]);
        } else {
            eArr[idx] = -1;
        }
    }
    __syncthreads();           // s_pres init + csh zero visible
    if (lane == 0) atomicOr(&s_pres, warpPres);
    __syncthreads();
    const unsigned pres = s_pres;

    const float* childsrc = child_is_leaf ? g_raw : g_emb;
    float* vrow = vsh + w * 512;
    float4* Wsh4 = (float4*)Wsh;

    for (int e = 0; e < 8; ++e) {
        if (!((pres >> e) & 1u)) continue;      // block-uniform skip
        __syncthreads();
        const float4* We4 = (const float4*)(edge_W + e * (D * D));
        for (int i = tid; i < 4096; i += 256) Wsh4[i] = We4[i];
        __syncthreads();

        unsigned m = 0u;
        #pragma unroll
        for (int idx = 0; idx < 16; ++idx)
            if (eArr[idx] == e) m |= (1u << idx);

        const float4 b4 = ((const float4*)(edge_b + e * D))[lane];

        while (m) {             // m uniform across warp
            int ids[4] = {-1, -1, -1, -1};
            if (m) { ids[0] = __ffs(m) - 1; m &= m - 1; }
            if (m) { ids[1] = __ffs(m) - 1; m &= m - 1; }
            if (m) { ids[2] = __ffs(m) - 1; m &= m - 1; }
            if (m) { ids[3] = __ffs(m) - 1; m &= m - 1; }

            #pragma unroll
            for (int t = 0; t < 4; ++t) {
                int idx = ids[t];
                if (idx >= 0) {
                    int i = w + (idx >> 1) * 8;
                    int c = 2 * (p0 + pbase + i) + 1 + (idx & 1);
                    float4 rv = ((const float4*)(childsrc + (size_t)c * D))[lane];
                    if (!child_is_leaf) {
                        rv.x = fmaxf(rv.x, 0.f); rv.y = fmaxf(rv.y, 0.f);
                        rv.z = fmaxf(rv.z, 0.f); rv.w = fmaxf(rv.w, 0.f);
                    }
                    ((float4*)(vrow + t * 128))[lane] = rv;
                }
            }
            __syncwarp();

            float a[4][4];
            #pragma unroll
            for (int t = 0; t < 4; ++t) { a[t][0]=0.f; a[t][1]=0.f; a[t][2]=0.f; a[t][3]=0.f; }
            #pragma unroll 4
            for (int k = 0; k < D; ++k) {
                float4 wv = Wsh4[k * 32 + lane];
                #pragma unroll
                for (int t = 0; t < 4; ++t) {
                    float vk = vrow[t * 128 + k];
                    a[t][0] += vk * wv.x; a[t][1] += vk * wv.y;
                    a[t][2] += vk * wv.z; a[t][3] += vk * wv.w;
                }
            }
            #pragma unroll
            for (int t = 0; t < 4; ++t) {
                int idx = ids[t];
                if (idx >= 0) {
                    int i = w + (idx >> 1) * 8;
                    float* cp = csh + i * 128 + lane * 4;
                    cp[0] += a[t][0] + b4.x;
                    cp[1] += a[t][1] + b4.y;
                    cp[2] += a[t][2] + b4.z;
                    cp[3] += a[t][3] + b4.w;
                }
            }
            __syncwarp();
        }
    }
    __syncthreads();

    const int nvalid = min(64, npar - pbase);
    for (int idx = tid; idx < nvalid * 128; idx += 256) {
        int i = idx >> 7, j = idx & 127;
        int p = p0 + pbase + i;
        float h = (g_raw[(size_t)p * D + j] + csh[idx]) * (1.0f / 3.0f);
        g_emb[(size_t)p * D + j] = h;
    }
}

// ---------------------------------------------------------------------------
// Scores: out[i] = dot(emb[i], score_W). emb = g_emb for internal, g_raw leaves.
// ---------------------------------------------------------------------------
__global__ void score_kernel(const float* __restrict__ score_W,
                             float* __restrict__ out)
{
    __shared__ float sW[D];
    const int tid = threadIdx.x;
    if (tid < D) sW[tid] = score_W[tid];
    __syncthreads();
    const int w = tid >> 5, lane = tid & 31;
    const float4 s4 = ((const float4*)sW)[lane];
    const int gw = blockIdx.x * 8 + w;
    const int nw = gridDim.x * 8;
    for (int node = gw; node < NTOT; node += nw) {
        const float* src = (node < LEAF0) ? g_emb : g_raw;
        float4 v = ((const float4*)(src + (size_t)node * D))[lane];
        float d = v.x * s4.x + v.y * s4.y + v.z * s4.z + v.w * s4.w;
        #pragma unroll
        for (int off = 16; off; off >>= 1)
            d += __shfl_xor_sync(0xffffffffu, d, off);
        if (lane == 0) out[node] = d;
    }
}

extern "C" void kernel_launch(void* const* d_in, const int* in_sizes, int n_in,
                              void* d_out, int out_size)
{
    const int*   data      = (const int*)  d_in[0];
    const int*   edges     = (const int*)  d_in[1];
    const float* data_vecs = (const float*)d_in[2];
    const float* data_W    = (const float*)d_in[3];
    const float* data_b    = (const float*)d_in[4];
    const float* edge_W    = (const float*)d_in[5];
    const float* edge_b    = (const float*)d_in[6];
    const float* score_W   = (const float*)d_in[7];
    float* out = (float*)d_out;
    (void)in_sizes; (void)n_in; (void)out_size;

    const int SMEM_E = (16384 + 4096 + 128) * 4;     // 82432 B
    const int SMEM_L = (16384 + 8192 + 4096) * 4;    // 114688 B (2 blocks/SM)

    cudaFuncSetAttribute(embed_kernel, cudaFuncAttributeMaxDynamicSharedMemorySize, SMEM_E);
    cudaFuncSetAttribute(level_kernel, cudaFuncAttributeMaxDynamicSharedMemorySize, SMEM_L);

    embed_kernel<<<592, 256, SMEM_E>>>(data, data_vecs, data_W, data_b);

    for (int l = 16; l >= 0; --l) {
        int npar = 1 << l;
        int p0 = npar - 1;
        int blocks = (npar + 63) / 64;
        level_kernel<<<blocks, 256, SMEM_L>>>(edges, edge_W, edge_b,
                                              p0, npar, (l == 16) ? 1 : 0);
    }

    score_kernel<<<592, 256>>>(score_W, out);
}

// round 2
// speedup vs baseline: 1.9275x; 1.9275x over previous
#include <cuda_runtime.h>

#define D 128
#define NTOT ((1 << 18) - 1)      // 262143
#define LEAF0 ((1 << 17) - 1)     // 131071

__device__ float g_raw[NTOT * D];      // embed output (= ret for leaves)
__device__ float g_emb[NTOT * D];      // h for internal nodes
__device__ float g_contrib[NTOT * D];  // per-child contribution
__device__ int   g_bucket[8 * (NTOT - 1)];
__device__ int   g_count[17 * 8];

// ---------------- f32x2 helpers (Blackwell packed fp32) ----------------
__device__ __forceinline__ void ffma2(unsigned long long& acc,
                                      unsigned long long a,
                                      unsigned long long b) {
    asm volatile("fma.rn.f32x2 %0, %1, %2, %0;" : "+l"(acc) : "l"(a), "l"(b));
}
__device__ __forceinline__ unsigned long long splat2(float v) {
    unsigned long long r;
    asm("mov.b64 %0, {%1, %1};" : "=l"(r) : "f"(v));
    return r;
}
__device__ __forceinline__ void unpack2(unsigned long long p, float& lo, float& hi) {
    asm("mov.b64 {%0, %1}, %2;" : "=f"(lo), "=f"(hi) : "l"(p));
}

// ---------------------------------------------------------------------------
// Zero bucket counters
// ---------------------------------------------------------------------------
__global__ void zero_kernel() {
    int i = threadIdx.x;
    if (i < 17 * 8) g_count[i] = 0;
}

// ---------------------------------------------------------------------------
// Bucket children of large levels (parent level >= 10) by (level, edge).
// ---------------------------------------------------------------------------
__global__ void bucket_kernel(const int* __restrict__ edges) {
    int c = blockIdx.x * blockDim.x + threadIdx.x + 2047;   // depth >= 11
    if (c >= NTOT) return;
    int d   = 31 - __clz(c + 1);        // child depth (11..17)
    int lev = d - 1;                    // parent level (10..16)
    int M    = 1 << d;
    int base = 8 * (M - 2);
    int e = edges[c];
    int slot = atomicAdd(&g_count[lev * 8 + e], 1);
    g_bucket[base + e * M + slot] = c;
}

// ---------------------------------------------------------------------------
// Embed: raw[i] = data_vecs[data[i]] @ data_W + data_b   (f32x2 inner loop)
// ---------------------------------------------------------------------------
__global__ void embed_kernel(const int* __restrict__ data,
                             const float* __restrict__ data_vecs,
                             const float* __restrict__ data_W,
                             const float* __restrict__ data_b)
{
    extern __shared__ float sm[];
    float* Wsh = sm;                       // 16384 floats
    float* vsh = sm + 16384;               // 8 warps * 512
    const int tid  = threadIdx.x;
    const int w    = tid >> 5;
    const int lane = tid & 31;

    {
        const float4* W4 = (const float4*)data_W;
        float4* Wd = (float4*)Wsh;
        for (int i = tid; i < 4096; i += 256) Wd[i] = W4[i];
    }
    __syncthreads();

    const ulonglong2* W2 = (const ulonglong2*)Wsh;
    float* vrow = vsh + w * 512;
    const float4 b4 = ((const float4*)data_b)[lane];

    const int gw = blockIdx.x * 8 + w;
    const int nw = gridDim.x * 8;
    for (int base = gw * 4; base < NTOT; base += nw * 4) {
        const int nvalid = min(4, NTOT - base);
        #pragma unroll
        for (int t = 0; t < 4; ++t) {
            int node = base + min(t, nvalid - 1);
            int v = data[node];
            ((float4*)(vrow + t * 128))[lane] =
                ((const float4*)(data_vecs + (size_t)v * D))[lane];
        }
        __syncwarp();

        unsigned long long acc[4][2];
        #pragma unroll
        for (int t = 0; t < 4; ++t) { acc[t][0] = 0ull; acc[t][1] = 0ull; }

        #pragma unroll 4
        for (int k = 0; k < D; ++k) {
            ulonglong2 wp = W2[k * 32 + lane];
            #pragma unroll
            for (int t = 0; t < 4; ++t) {
                unsigned long long s = splat2(vrow[t * 128 + k]);
                ffma2(acc[t][0], s, wp.x);
                ffma2(acc[t][1], s, wp.y);
            }
        }
        #pragma unroll
        for (int t = 0; t < 4; ++t) {
            if (t < nvalid) {
                float x, y, z, u;
                unpack2(acc[t][0], x, y);
                unpack2(acc[t][1], z, u);
                float4 o = make_float4(x + b4.x, y + b4.y, z + b4.z, u + b4.w);
                ((float4*)(g_raw + (size_t)(base + t) * D))[lane] = o;
            }
        }
        __syncwarp();
    }
}

// ---------------------------------------------------------------------------
// Bucketed per-edge GEMV for large levels. Block handles edge (bid & 7),
// loads edge_W[e] once, streams 256-child tiles. contrib[c] = b_e + ret_c @ W_e
// ---------------------------------------------------------------------------
__global__ void edge_gemm_kernel(const float* __restrict__ edge_W,
                                 const float* __restrict__ edge_b,
                                 int bucket_base, int M,
                                 const int* __restrict__ counts,
                                 int child_is_leaf)
{
    const int e  = blockIdx.x & 7;
    const int bi = blockIdx.x >> 3;
    const int nb = gridDim.x >> 3;
    const int count = counts[e];
    if (bi * 256 >= count) return;

    extern __shared__ float sm[];
    float* Wsh = sm;                 // 16384 floats
    float* vsh = sm + 16384;         // 8 * 512

    const int tid  = threadIdx.x;
    const int w    = tid >> 5;
    const int lane = tid & 31;

    {
        const float4* We4 = (const float4*)(edge_W + (size_t)e * D * D);
        float4* Wd = (float4*)Wsh;
        for (int i = tid; i < 4096; i += 256) Wd[i] = We4[i];
    }
    __syncthreads();

    const ulonglong2* W2 = (const ulonglong2*)Wsh;
    float* vrow = vsh + w * 512;
    const float4 b4 = ((const float4*)(edge_b + e * D))[lane];
    const int* list = g_bucket + bucket_base + e * M;
    const float* childsrc = child_is_leaf ? g_raw : g_emb;

    for (int start = bi * 256; start < count; start += nb * 256) {
        #pragma unroll 1
        for (int batch = 0; batch < 8; ++batch) {
            const int j0 = start + w * 32 + batch * 4;
            if (j0 >= count) break;                 // warp-uniform
            const int nv = min(4, count - j0);
            int cid[4];
            #pragma unroll
            for (int t = 0; t < 4; ++t) {
                cid[t] = list[min(j0 + t, count - 1)];
                float4 rv = ((const float4*)(childsrc + (size_t)cid[t] * D))[lane];
                if (!child_is_leaf) {
                    rv.x = fmaxf(rv.x, 0.f); rv.y = fmaxf(rv.y, 0.f);
                    rv.z = fmaxf(rv.z, 0.f); rv.w = fmaxf(rv.w, 0.f);
                }
                ((float4*)(vrow + t * 128))[lane] = rv;
            }
            __syncwarp();

            unsigned long long acc[4][2];
            #pragma unroll
            for (int t = 0; t < 4; ++t) { acc[t][0] = 0ull; acc[t][1] = 0ull; }

            #pragma unroll 4
            for (int k = 0; k < D; ++k) {
                ulonglong2 wp = W2[k * 32 + lane];
                #pragma unroll
                for (int t = 0; t < 4; ++t) {
                    unsigned long long s = splat2(vrow[t * 128 + k]);
                    ffma2(acc[t][0], s, wp.x);
                    ffma2(acc[t][1], s, wp.y);
                }
            }
            #pragma unroll
            for (int t = 0; t < 4; ++t) {
                if (t < nv) {
                    float x, y, z, u;
                    unpack2(acc[t][0], x, y);
                    unpack2(acc[t][1], z, u);
                    float4 o = make_float4(x + b4.x, y + b4.y, z + b4.z, u + b4.w);
                    ((float4*)(g_contrib + (size_t)cid[t] * D))[lane] = o;
                }
            }
            __syncwarp();
        }
    }
}

// ---------------------------------------------------------------------------
// Combine: emb[p] = (raw[p] + contrib[2p+1] + contrib[2p+2]) / 3
// ---------------------------------------------------------------------------
__global__ void combine_kernel(int p0, int npar) {
    int idx = blockIdx.x * blockDim.x + threadIdx.x;   // over npar * 32 float4
    if (idx >= npar * 32) return;
    int i = idx >> 5, q = idx & 31;
    int p = p0 + i;
    float4 r  = ((const float4*)(g_raw     + (size_t)p * D))[q];
    float4 c1 = ((const float4*)(g_contrib + (size_t)(2 * p + 1) * D))[q];
    float4 c2 = ((const float4*)(g_contrib + (size_t)(2 * p + 2) * D))[q];
    float4 h = make_float4((r.x + c1.x + c2.x) * (1.f / 3.f),
                           (r.y + c1.y + c2.y) * (1.f / 3.f),
                           (r.z + c1.z + c2.z) * (1.f / 3.f),
                           (r.w + c1.w + c2.w) * (1.f / 3.f));
    ((float4*)(g_emb + (size_t)p * D))[q] = h;
}

// ---------------------------------------------------------------------------
// Small levels (l <= 9): one block per parent, fused matvecs + combine.
// Children are always internal nodes here.
// ---------------------------------------------------------------------------
__global__ void small_level_kernel(const int* __restrict__ edges,
                                   const float* __restrict__ edge_W,
                                   const float* __restrict__ edge_b,
                                   int p0)
{
    const int p = p0 + blockIdx.x;
    const int tid = threadIdx.x;          // 128 threads
    const int c1 = 2 * p + 1, c2 = 2 * p + 2;
    __shared__ float v1[D], v2[D];
    __shared__ int se[2];
    if (tid < 2) se[tid] = edges[tid ? c2 : c1];
    v1[tid] = fmaxf(g_emb[(size_t)c1 * D + tid], 0.f);
    v2[tid] = fmaxf(g_emb[(size_t)c2 * D + tid], 0.f);
    __syncthreads();
    const int e1 = se[0], e2 = se[1];
    const float* W1 = edge_W + (size_t)e1 * D * D + tid;
    const float* W2 = edge_W + (size_t)e2 * D * D + tid;
    float acc = edge_b[e1 * D + tid] + edge_b[e2 * D + tid];
    #pragma unroll 8
    for (int k = 0; k < D; ++k)
        acc += v1[k] * W1[k * D] + v2[k] * W2[k * D];
    float h = (g_raw[(size_t)p * D + tid] + acc) * (1.f / 3.f);
    g_emb[(size_t)p * D + tid] = h;
}

// ---------------------------------------------------------------------------
// Scores
// ---------------------------------------------------------------------------
__global__ void score_kernel(const float* __restrict__ score_W,
                             float* __restrict__ out)
{
    __shared__ float sW[D];
    const int tid = threadIdx.x;
    if (tid < D) sW[tid] = score_W[tid];
    __syncthreads();
    const int w = tid >> 5, lane = tid & 31;
    const float4 s4 = ((const float4*)sW)[lane];
    const int gw = blockIdx.x * 8 + w;
    const int nw = gridDim.x * 8;
    for (int node = gw; node < NTOT; node += nw) {
        const float* src = (node < LEAF0) ? g_emb : g_raw;
        float4 v = ((const float4*)(src + (size_t)node * D))[lane];
        float d = v.x * s4.x + v.y * s4.y + v.z * s4.z + v.w * s4.w;
        #pragma unroll
        for (int off = 16; off; off >>= 1)
            d += __shfl_xor_sync(0xffffffffu, d, off);
        if (lane == 0) out[node] = d;
    }
}

extern "C" void kernel_launch(void* const* d_in, const int* in_sizes, int n_in,
                              void* d_out, int out_size)
{
    const int*   data      = (const int*)  d_in[0];
    const int*   edges     = (const int*)  d_in[1];
    const float* data_vecs = (const float*)d_in[2];
    const float* data_W    = (const float*)d_in[3];
    const float* data_b    = (const float*)d_in[4];
    const float* edge_W    = (const float*)d_in[5];
    const float* edge_b    = (const float*)d_in[6];
    const float* score_W   = (const float*)d_in[7];
    float* out = (float*)d_out;
    (void)in_sizes; (void)n_in; (void)out_size;

    const int SMEM_BIG = (16384 + 4096) * 4;    // 81920 B -> 2 blocks/SM

    cudaFuncSetAttribute(embed_kernel, cudaFuncAttributeMaxDynamicSharedMemorySize, SMEM_BIG);
    cudaFuncSetAttribute(edge_gemm_kernel, cudaFuncAttributeMaxDynamicSharedMemorySize, SMEM_BIG);

    int* d_count;
    cudaGetSymbolAddress((void**)&d_count, g_count);

    zero_kernel<<<1, 160>>>();
    bucket_kernel<<<(NTOT - 2047 + 255) / 256, 256>>>(edges);
    embed_kernel<<<296, 256, SMEM_BIG>>>(data, data_vecs, data_W, data_b);

    // Large levels: l = 16 .. 10 (bucketed GEMV + combine)
    for (int l = 16; l >= 10; --l) {
        int d = l + 1;
        int M = 1 << d;
        int base = 8 * (M - 2);
        int npar = 1 << l;
        int p0 = npar - 1;
        edge_gemm_kernel<<<296, 256, SMEM_BIG>>>(edge_W, edge_b, base, M,
                                                 d_count + l * 8, (l == 16) ? 1 : 0);
        combine_kernel<<<(npar * 32 + 255) / 256, 256>>>(p0, npar);
    }

    // Small levels: l = 9 .. 0 (fused per-parent)
    for (int l = 9; l >= 0; --l) {
        int npar = 1 << l;
        int p0 = npar - 1;
        small_level_kernel<<<npar, 128>>>(edges, edge_W, edge_b, p0);
    }

    score_kernel<<<592, 256>>>(score_W, out);
}

// round 3
// speedup vs baseline: 2.7254x; 1.4139x over previous
#include <cuda_runtime.h>

#define D 128
#define NTOT ((1 << 18) - 1)      // 262143
#define LEAF0 ((1 << 17) - 1)     // 131071

__device__ float g_raw[NTOT * D];      // embed output (= ret for leaves)
__device__ float g_emb[NTOT * D];      // h for internal nodes
__device__ float g_contrib[NTOT * D];  // per-child contribution
__device__ int   g_bucket[8 * (NTOT - 1)];
__device__ int   g_count[17 * 8];

// ---------------- f32x2 helpers (Blackwell packed fp32) ----------------
__device__ __forceinline__ void ffma2(unsigned long long& acc,
                                      unsigned long long a,
                                      unsigned long long b) {
    asm volatile("fma.rn.f32x2 %0, %1, %2, %0;" : "+l"(acc) : "l"(a), "l"(b));
}
__device__ __forceinline__ unsigned long long splat2(float v) {
    unsigned long long r;
    asm("mov.b64 %0, {%1, %1};" : "=l"(r) : "f"(v));
    return r;
}
__device__ __forceinline__ void unpack2(unsigned long long p, float& lo, float& hi) {
    asm("mov.b64 {%0, %1}, %2;" : "=f"(lo), "=f"(hi) : "l"(p));
}

__global__ void zero_kernel() {
    int i = threadIdx.x;
    if (i < 17 * 8) g_count[i] = 0;
}

// Bucket children of large levels (parent level >= 10) by (level, edge).
__global__ void bucket_kernel(const int* __restrict__ edges) {
    int c = blockIdx.x * blockDim.x + threadIdx.x + 2047;   // depth >= 11
    if (c >= NTOT) return;
    int d   = 31 - __clz(c + 1);        // child depth (11..17)
    int lev = d - 1;                    // parent level (10..16)
    int M    = 1 << d;
    int base = 8 * (M - 2);
    int e = edges[c];
    int slot = atomicAdd(&g_count[lev * 8 + e], 1);
    g_bucket[base + e * M + slot] = c;
}

// ---------------------------------------------------------------------------
// Embed: raw[i] = data_vecs[data[i]] @ data_W + data_b
// Register-blocked: thread tile = 8 rows x 4 cols, FFMA2 inner loop.
// ---------------------------------------------------------------------------
__global__ void embed_kernel(const int* __restrict__ data,
                             const float* __restrict__ data_vecs,
                             const float* __restrict__ data_W,
                             const float* __restrict__ data_b)
{
    extern __shared__ float sm[];
    float* Wsh = sm;                 // 16384 floats (64 KB)
    float* Ash = sm + 16384;         // 64 x 128 floats (32 KB)

    const int tid = threadIdx.x;
    const int tx  = tid & 31;
    const int ty  = tid >> 5;

    {
        const float4* W4 = (const float4*)data_W;
        float4* Wd = (float4*)Wsh;
        for (int i = tid; i < 4096; i += 256) Wd[i] = W4[i];
    }
    __syncthreads();

    const ulonglong2* W2 = (const ulonglong2*)Wsh;
    const float4 b4 = ((const float4*)data_b)[tx];
    float4* Arow = (float4*)(Ash + ty * 1024);   // this warp's 8 rows

    const int ntile = (NTOT + 63) >> 6;          // 4096
    for (int tile = blockIdx.x; tile < ntile; tile += gridDim.x) {
        const int base = tile * 64 + ty * 8;
        int nid[8];
        #pragma unroll
        for (int r = 0; r < 8; ++r) {
            nid[r] = min(base + r, NTOT - 1);
            int v = __ldg(&data[nid[r]]);
            Arow[r * 32 + tx] = ((const float4*)(data_vecs + (size_t)v * D))[tx];
        }
        __syncwarp();

        unsigned long long acc[8][2];
        #pragma unroll
        for (int r = 0; r < 8; ++r) { acc[r][0] = 0ull; acc[r][1] = 0ull; }

        #pragma unroll 2
        for (int kq = 0; kq < 32; ++kq) {
            ulonglong2 w0 = W2[(kq * 4 + 0) * 32 + tx];
            ulonglong2 w1 = W2[(kq * 4 + 1) * 32 + tx];
            ulonglong2 w2 = W2[(kq * 4 + 2) * 32 + tx];
            ulonglong2 w3 = W2[(kq * 4 + 3) * 32 + tx];
            #pragma unroll
            for (int r = 0; r < 8; ++r) {
                float4 v = Arow[r * 32 + kq];
                unsigned long long s;
                s = splat2(v.x); ffma2(acc[r][0], s, w0.x); ffma2(acc[r][1], s, w0.y);
                s = splat2(v.y); ffma2(acc[r][0], s, w1.x); ffma2(acc[r][1], s, w1.y);
                s = splat2(v.z); ffma2(acc[r][0], s, w2.x); ffma2(acc[r][1], s, w2.y);
                s = splat2(v.w); ffma2(acc[r][0], s, w3.x); ffma2(acc[r][1], s, w3.y);
            }
        }

        #pragma unroll
        for (int r = 0; r < 8; ++r) {
            float x, y, z, u;
            unpack2(acc[r][0], x, y);
            unpack2(acc[r][1], z, u);
            float4 o = make_float4(x + b4.x, y + b4.y, z + b4.z, u + b4.w);
            ((float4*)(g_raw + (size_t)nid[r] * D))[tx] = o;
        }
        __syncwarp();
    }
}

// ---------------------------------------------------------------------------
// Bucketed per-edge GEMM, register-blocked. Block handles edge bid/nb,
// grid-strides 64-child tiles. contrib[c] = b_e + ret_c @ W_e
// ---------------------------------------------------------------------------
__global__ void edge_gemm_kernel(const float* __restrict__ edge_W,
                                 const float* __restrict__ edge_b,
                                 int bucket_base, int M,
                                 const int* __restrict__ counts,
                                 int child_is_leaf, int nb)
{
    const int e  = blockIdx.x / nb;
    const int bi = blockIdx.x % nb;
    const int count = counts[e];
    if (count == 0) return;

    extern __shared__ float sm[];
    float* Wsh = sm;                 // 16384 floats
    float* Ash = sm + 16384;         // 64 x 128 floats

    const int tid = threadIdx.x;
    const int tx  = tid & 31;
    const int ty  = tid >> 5;

    {
        const float4* We4 = (const float4*)(edge_W + (size_t)e * D * D);
        float4* Wd = (float4*)Wsh;
        for (int i = tid; i < 4096; i += 256) Wd[i] = We4[i];
    }
    __syncthreads();

    const ulonglong2* W2 = (const ulonglong2*)Wsh;
    const float4 b4 = ((const float4*)(edge_b + e * D))[tx];
    const int* list = g_bucket + bucket_base + e * M;
    const float* childsrc = child_is_leaf ? g_raw : g_emb;
    float4* Arow = (float4*)(Ash + ty * 1024);

    const int ntile = (count + 63) >> 6;
    for (int tile = bi; tile < ntile; tile += nb) {
        const int base = tile * 64 + ty * 8;
        int cid[8];
        #pragma unroll
        for (int r = 0; r < 8; ++r) {
            cid[r] = list[min(base + r, count - 1)];
            float4 rv = ((const float4*)(childsrc + (size_t)cid[r] * D))[tx];
            if (!child_is_leaf) {
                rv.x = fmaxf(rv.x, 0.f); rv.y = fmaxf(rv.y, 0.f);
                rv.z = fmaxf(rv.z, 0.f); rv.w = fmaxf(rv.w, 0.f);
            }
            Arow[r * 32 + tx] = rv;
        }
        __syncwarp();

        unsigned long long acc[8][2];
        #pragma unroll
        for (int r = 0; r < 8; ++r) { acc[r][0] = 0ull; acc[r][1] = 0ull; }

        #pragma unroll 2
        for (int kq = 0; kq < 32; ++kq) {
            ulonglong2 w0 = W2[(kq * 4 + 0) * 32 + tx];
            ulonglong2 w1 = W2[(kq * 4 + 1) * 32 + tx];
            ulonglong2 w2 = W2[(kq * 4 + 2) * 32 + tx];
            ulonglong2 w3 = W2[(kq * 4 + 3) * 32 + tx];
            #pragma unroll
            for (int r = 0; r < 8; ++r) {
                float4 v = Arow[r * 32 + kq];
                unsigned long long s;
                s = splat2(v.x); ffma2(acc[r][0], s, w0.x); ffma2(acc[r][1], s, w0.y);
                s = splat2(v.y); ffma2(acc[r][0], s, w1.x); ffma2(acc[r][1], s, w1.y);
                s = splat2(v.z); ffma2(acc[r][0], s, w2.x); ffma2(acc[r][1], s, w2.y);
                s = splat2(v.w); ffma2(acc[r][0], s, w3.x); ffma2(acc[r][1], s, w3.y);
            }
        }

        #pragma unroll
        for (int r = 0; r < 8; ++r) {
            float x, y, z, u;
            unpack2(acc[r][0], x, y);
            unpack2(acc[r][1], z, u);
            float4 o = make_float4(x + b4.x, y + b4.y, z + b4.z, u + b4.w);
            ((float4*)(g_contrib + (size_t)cid[r] * D))[tx] = o;
        }
        __syncwarp();
    }
}

// emb[p] = (raw[p] + contrib[2p+1] + contrib[2p+2]) / 3
__global__ void combine_kernel(int p0, int npar) {
    int idx = blockIdx.x * blockDim.x + threadIdx.x;
    if (idx >= npar * 32) return;
    int i = idx >> 5, q = idx & 31;
    int p = p0 + i;
    float4 r  = ((const float4*)(g_raw     + (size_t)p * D))[q];
    float4 c1 = ((const float4*)(g_contrib + (size_t)(2 * p + 1) * D))[q];
    float4 c2 = ((const float4*)(g_contrib + (size_t)(2 * p + 2) * D))[q];
    float4 h = make_float4((r.x + c1.x + c2.x) * (1.f / 3.f),
                           (r.y + c1.y + c2.y) * (1.f / 3.f),
                           (r.z + c1.z + c2.z) * (1.f / 3.f),
                           (r.w + c1.w + c2.w) * (1.f / 3.f));
    ((float4*)(g_emb + (size_t)p * D))[q] = h;
}

// Small levels (l <= 9): one block per parent, fused matvecs + combine.
__global__ void small_level_kernel(const int* __restrict__ edges,
                                   const float* __restrict__ edge_W,
                                   const float* __restrict__ edge_b,
                                   int p0)
{
    const int p = p0 + blockIdx.x;
    const int tid = threadIdx.x;          // 128 threads
    const int c1 = 2 * p + 1, c2 = 2 * p + 2;
    __shared__ float v1[D], v2[D];
    __shared__ int se[2];
    if (tid < 2) se[tid] = edges[tid ? c2 : c1];
    v1[tid] = fmaxf(g_emb[(size_t)c1 * D + tid], 0.f);
    v2[tid] = fmaxf(g_emb[(size_t)c2 * D + tid], 0.f);
    __syncthreads();
    const int e1 = se[0], e2 = se[1];
    const float* W1 = edge_W + (size_t)e1 * D * D + tid;
    const float* W2 = edge_W + (size_t)e2 * D * D + tid;
    float acc = edge_b[e1 * D + tid] + edge_b[e2 * D + tid];
    #pragma unroll 8
    for (int k = 0; k < D; ++k)
        acc += v1[k] * W1[k * D] + v2[k] * W2[k * D];
    float h = (g_raw[(size_t)p * D + tid] + acc) * (1.f / 3.f);
    g_emb[(size_t)p * D + tid] = h;
}

__global__ void score_kernel(const float* __restrict__ score_W,
                             float* __restrict__ out)
{
    __shared__ float sW[D];
    const int tid = threadIdx.x;
    if (tid < D) sW[tid] = score_W[tid];
    __syncthreads();
    const int w = tid >> 5, lane = tid & 31;
    const float4 s4 = ((const float4*)sW)[lane];
    const int gw = blockIdx.x * 8 + w;
    const int nw = gridDim.x * 8;
    for (int node = gw; node < NTOT; node += nw) {
        const float* src = (node < LEAF0) ? g_emb : g_raw;
        float4 v = ((const float4*)(src + (size_t)node * D))[lane];
        float d = v.x * s4.x + v.y * s4.y + v.z * s4.z + v.w * s4.w;
        #pragma unroll
        for (int off = 16; off; off >>= 1)
            d += __shfl_xor_sync(0xffffffffu, d, off);
        if (lane == 0) out[node] = d;
    }
}

extern "C" void kernel_launch(void* const* d_in, const int* in_sizes, int n_in,
                              void* d_out, int out_size)
{
    const int*   data      = (const int*)  d_in[0];
    const int*   edges     = (const int*)  d_in[1];
    const float* data_vecs = (const float*)d_in[2];
    const float* data_W    = (const float*)d_in[3];
    const float* data_b    = (const float*)d_in[4];
    const float* edge_W    = (const float*)d_in[5];
    const float* edge_b    = (const float*)d_in[6];
    const float* score_W   = (const float*)d_in[7];
    float* out = (float*)d_out;
    (void)in_sizes; (void)n_in; (void)out_size;

    const int SMEM_GEMM = (16384 + 8192) * 4;    // 98304 B -> 2 blocks/SM

    cudaFuncSetAttribute(embed_kernel, cudaFuncAttributeMaxDynamicSharedMemorySize, SMEM_GEMM);
    cudaFuncSetAttribute(edge_gemm_kernel, cudaFuncAttributeMaxDynamicSharedMemorySize, SMEM_GEMM);

    int* d_count;
    cudaGetSymbolAddress((void**)&d_count, g_count);

    zero_kernel<<<1, 160>>>();
    bucket_kernel<<<(NTOT - 2047 + 255) / 256, 256>>>(edges);
    embed_kernel<<<592, 256, SMEM_GEMM>>>(data, data_vecs, data_W, data_b);

    // Large levels: l = 16 .. 10 (bucketed GEMM + combine)
    for (int l = 16; l >= 10; --l) {
        int d = l + 1;
        int M2 = 1 << d;            // children at this level
        int base = 8 * (M2 - 2);
        int npar = 1 << l;
        int p0 = npar - 1;
        int tiles_pe = M2 >> 9;     // expected tiles per edge
        int nb = tiles_pe + 2; if (nb > 37) nb = 37;
        edge_gemm_kernel<<<8 * nb, 256, SMEM_GEMM>>>(edge_W, edge_b, base, M2,
                                                     d_count + l * 8,
                                                     (l == 16) ? 1 : 0, nb);
        combine_kernel<<<(npar * 32 + 255) / 256, 256>>>(p0, npar);
    }

    // Small levels: l = 9 .. 0
    for (int l = 9; l >= 0; --l) {
        int npar = 1 << l;
        int p0 = npar - 1;
        small_level_kernel<<<npar, 128>>>(edges, edge_W, edge_b, p0);
    }

    score_kernel<<<592, 256>>>(score_W, out);
}